// round 4
// baseline (speedup 1.0000x reference)
#include <cuda_runtime.h>
#include <math_constants.h>

// Problem shape (fixed by the dataset)
#define BB 4
#define HH 16
#define SS 2048
#define DD 64

#define BM 64    // query rows per CTA
#define BN 64    // key/value columns per tile
#define PSS 68   // padded ps row stride (floats): kills stride-64 bank conflicts

// Dynamic smem layout (floats):
//   qst [DD][BM]   Q tile transposed: qst[d][r]
//   ks  [DD][BN]   K tile: ks[d][c]
//   vs  [BN][DD]   V tile: vs[c][d]
//   ps  [BM][PSS]  P tile (padded)
#define SMEM_FLOATS (DD*BM + DD*BN + BN*DD + BM*PSS)

typedef unsigned long long ull;

// sm_103a packed f32x2 math: 2 FMA per issue slot, bit-exact vs scalar fma.rn
__device__ __forceinline__ void fma2(ull &d, ull a, ull b) {
    asm("fma.rn.f32x2 %0, %1, %2, %0;" : "+l"(d) : "l"(a), "l"(b));
}
__device__ __forceinline__ ull pk2(float x) {
    ull r; asm("mov.b64 %0, {%1, %1};" : "=l"(r) : "f"(x)); return r;
}
__device__ __forceinline__ void mul2(ull &d, ull a) {
    asm("mul.rn.f32x2 %0, %0, %1;" : "+l"(d) : "l"(a));
}
__device__ __forceinline__ float2 upk2(ull v) {
    float2 r; asm("mov.b64 {%0, %1}, %2;" : "=f"(r.x), "=f"(r.y) : "l"(v)); return r;
}

__global__ __launch_bounds__(128, 3)
void attn_fused_kernel(const float* __restrict__ q,
                       const float* __restrict__ k,
                       const float* __restrict__ v,
                       const int*   __restrict__ mask,
                       float* __restrict__ out_o,   // may be null
                       float* __restrict__ out_s)   // may be null
{
    extern __shared__ float sm[];
    float* qst = sm;                       // [DD][BM]
    float* ks  = qst + DD*BM;              // [DD][BN]
    float* vs  = ks  + DD*BN;              // [BN][DD]
    float* ps  = vs  + BN*DD;              // [BM][PSS]

    const int tid = threadIdx.x;
    const int tx = tid & 7;                // 0..7  -> 8 columns each
    const int ty = tid >> 3;               // 0..15 -> 4 rows each
    const int rb = blockIdx.x;             // row block (0..31)
    const int h  = blockIdx.y;
    const int b  = blockIdx.z;

    const size_t bh = (size_t)b * HH + h;
    const float* qp = q + (bh * SS + (size_t)rb * BM) * DD;  // [BM][DD]
    const float* kp = k + bh * (size_t)DD * SS;              // [DD][SS]
    const float* vp = v + bh * (size_t)SS * DD;              // [SS][DD]
    const int*   mp = mask + ((size_t)b * SS + (size_t)rb * BM) * SS; // [BM][SS]
    float* osp = out_s ? (out_s + (bh * SS + (size_t)rb * BM) * SS) : (float*)0;

    // ---- Load Q tile, transposed into smem (one-time) ----
    #pragma unroll
    for (int it = 0; it < 8; ++it) {
        int id4 = tid + it * 128;
        int r  = id4 >> 4;
        int d4 = (id4 & 15) * 4;
        float4 qv = *(const float4*)(qp + (size_t)r * DD + d4);
        qst[(d4 + 0) * BM + r] = qv.x;
        qst[(d4 + 1) * BM + r] = qv.y;
        qst[(d4 + 2) * BM + r] = qv.z;
        qst[(d4 + 3) * BM + r] = qv.w;
    }

    // ---- Online-softmax state ----
    float m_run[4], l_run[4];
    ull o2[4][4];                          // 4 rows x 8 cols (4 f32x2 pairs)
    #pragma unroll
    for (int i = 0; i < 4; ++i) {
        m_run[i] = -CUDART_INF_F;
        l_run[i] = 0.f;
        #pragma unroll
        for (int jj = 0; jj < 4; ++jj) o2[i][jj] = 0ull;
    }

    for (int jt = 0; jt < SS / BN; ++jt) {
        const int s0 = jt * BN;

        __syncthreads();   // previous iter's PV readers done before overwriting tiles
        // ---- Load K and V tiles (coalesced float4) ----
        #pragma unroll
        for (int it = 0; it < 8; ++it) {
            int id4 = tid + it * 128;
            int r  = id4 >> 4;
            int c4 = (id4 & 15) * 4;
            *(float4*)(ks + r * BN + c4) = *(const float4*)(kp + (size_t)r * SS + s0 + c4);
            *(float4*)(vs + r * DD + c4) = *(const float4*)(vp + (size_t)(s0 + r) * DD + c4);
        }
        __syncthreads();

        // ---- S tile = Q*K : 4 rows x 8 cols per thread, packed f32x2 ----
        ull s2[4][4];
        #pragma unroll
        for (int i = 0; i < 4; ++i)
            #pragma unroll
            for (int jj = 0; jj < 4; ++jj) s2[i][jj] = 0ull;

        #pragma unroll 4
        for (int d = 0; d < DD; ++d) {
            const float4 a4 = *(const float4*)(qst + d * BM + 4 * ty);
            const ulonglong2 b0 = *(const ulonglong2*)(ks + d * BN + 8 * tx);
            const ulonglong2 b1 = *(const ulonglong2*)(ks + d * BN + 8 * tx + 4);
            ull ad0 = pk2(a4.x), ad1 = pk2(a4.y), ad2 = pk2(a4.z), ad3 = pk2(a4.w);
            fma2(s2[0][0], ad0, b0.x); fma2(s2[0][1], ad0, b0.y);
            fma2(s2[0][2], ad0, b1.x); fma2(s2[0][3], ad0, b1.y);
            fma2(s2[1][0], ad1, b0.x); fma2(s2[1][1], ad1, b0.y);
            fma2(s2[1][2], ad1, b1.x); fma2(s2[1][3], ad1, b1.y);
            fma2(s2[2][0], ad2, b0.x); fma2(s2[2][1], ad2, b0.y);
            fma2(s2[2][2], ad2, b1.x); fma2(s2[2][3], ad2, b1.y);
            fma2(s2[3][0], ad3, b0.x); fma2(s2[3][1], ad3, b0.y);
            fma2(s2[3][2], ad3, b1.x); fma2(s2[3][3], ad3, b1.y);
        }

        // ---- Mask, scale, write scores, online softmax update, stage P ----
        #pragma unroll
        for (int ri = 0; ri < 4; ++ri) {
            const int rloc = 4 * ty + ri;
            float sv[8];
            {
                float2 t;
                t = upk2(s2[ri][0]); sv[0] = t.x; sv[1] = t.y;
                t = upk2(s2[ri][1]); sv[2] = t.x; sv[3] = t.y;
                t = upk2(s2[ri][2]); sv[4] = t.x; sv[5] = t.y;
                t = upk2(s2[ri][3]); sv[6] = t.x; sv[7] = t.y;
            }
            const int4 m0 = *(const int4*)(mp + (size_t)rloc * SS + s0 + 8 * tx);
            const int4 m1 = *(const int4*)(mp + (size_t)rloc * SS + s0 + 8 * tx + 4);
            sv[0] = (m0.x == 0) ? -1e10f : sv[0] * 0.125f;
            sv[1] = (m0.y == 0) ? -1e10f : sv[1] * 0.125f;
            sv[2] = (m0.z == 0) ? -1e10f : sv[2] * 0.125f;
            sv[3] = (m0.w == 0) ? -1e10f : sv[3] * 0.125f;
            sv[4] = (m1.x == 0) ? -1e10f : sv[4] * 0.125f;
            sv[5] = (m1.y == 0) ? -1e10f : sv[5] * 0.125f;
            sv[6] = (m1.z == 0) ? -1e10f : sv[6] * 0.125f;
            sv[7] = (m1.w == 0) ? -1e10f : sv[7] * 0.125f;
            if (osp) {
                *(float4*)(osp + (size_t)rloc * SS + s0 + 8 * tx) =
                    make_float4(sv[0], sv[1], sv[2], sv[3]);
                *(float4*)(osp + (size_t)rloc * SS + s0 + 8 * tx + 4) =
                    make_float4(sv[4], sv[5], sv[6], sv[7]);
            }

            // row max across the 8 threads of this row group (lanes are consecutive)
            float tm = fmaxf(fmaxf(fmaxf(sv[0], sv[1]), fmaxf(sv[2], sv[3])),
                             fmaxf(fmaxf(sv[4], sv[5]), fmaxf(sv[6], sv[7])));
            #pragma unroll
            for (int off = 4; off >= 1; off >>= 1)
                tm = fmaxf(tm, __shfl_xor_sync(0xffffffffu, tm, off));

            float mn   = fmaxf(m_run[ri], tm);
            float corr = __expf(m_run[ri] - mn);   // exp(-inf)=0 on first tile
            m_run[ri]  = mn;

            float p[8];
            float rs = 0.f;
            #pragma unroll
            for (int jj = 0; jj < 8; ++jj) { p[jj] = __expf(sv[jj] - mn); rs += p[jj]; }
            #pragma unroll
            for (int off = 4; off >= 1; off >>= 1)
                rs += __shfl_xor_sync(0xffffffffu, rs, off);

            l_run[ri] = l_run[ri] * corr + rs;
            ull c2 = pk2(corr);
            #pragma unroll
            for (int jj = 0; jj < 4; ++jj) mul2(o2[ri][jj], c2);

            *(float4*)(ps + rloc * PSS + 8 * tx)     = make_float4(p[0], p[1], p[2], p[3]);
            *(float4*)(ps + rloc * PSS + 8 * tx + 4) = make_float4(p[4], p[5], p[6], p[7]);
        }
        __syncthreads();   // ps ready

        // ---- O += P*V : packed f32x2, P loaded as float4 per 4 columns ----
        #pragma unroll 2
        for (int c4 = 0; c4 < BN; c4 += 4) {
            float pr[4][4];
            #pragma unroll
            for (int i = 0; i < 4; ++i)
                *(float4*)pr[i] = *(const float4*)(ps + (4 * ty + i) * PSS + c4);
            #pragma unroll
            for (int cc = 0; cc < 4; ++cc) {
                const int c = c4 + cc;
                const ulonglong2 v0 = *(const ulonglong2*)(vs + c * DD + 8 * tx);
                const ulonglong2 v1 = *(const ulonglong2*)(vs + c * DD + 8 * tx + 4);
                #pragma unroll
                for (int i = 0; i < 4; ++i) {
                    ull pd = pk2(pr[i][cc]);
                    fma2(o2[i][0], pd, v0.x); fma2(o2[i][1], pd, v0.y);
                    fma2(o2[i][2], pd, v1.x); fma2(o2[i][3], pd, v1.y);
                }
            }
        }
    }

    // ---- Normalize and write O ----
    if (out_o) {
        float* op = out_o + (bh * SS + (size_t)rb * BM) * DD;
        #pragma unroll
        for (int ri = 0; ri < 4; ++ri) {
            float inv = 1.0f / l_run[ri];
            float2 t0 = upk2(o2[ri][0]);
            float2 t1 = upk2(o2[ri][1]);
            float2 t2 = upk2(o2[ri][2]);
            float2 t3 = upk2(o2[ri][3]);
            *(float4*)(op + (size_t)(4 * ty + ri) * DD + 8 * tx) =
                make_float4(t0.x * inv, t0.y * inv, t1.x * inv, t1.y * inv);
            *(float4*)(op + (size_t)(4 * ty + ri) * DD + 8 * tx + 4) =
                make_float4(t2.x * inv, t2.y * inv, t3.x * inv, t3.y * inv);
        }
    }
}

extern "C" void kernel_launch(void* const* d_in, const int* in_sizes, int n_in,
                              void* d_out, int out_size)
{
    const float* q    = (const float*)d_in[0];
    const float* k    = (const float*)d_in[1];
    const float* v    = (const float*)d_in[2];
    const int*   mask = (const int*)  d_in[3];

    const long long OUT_O_N = (long long)BB * HH * SS * DD;   // 8388608
    const long long OUT_S_N = (long long)BB * HH * SS * SS;   // 268435456

    float* o_ptr = 0;
    float* s_ptr = 0;
    if ((long long)out_size == OUT_O_N + OUT_S_N) {
        o_ptr = (float*)d_out;
        s_ptr = (float*)d_out + OUT_O_N;
    } else if ((long long)out_size == OUT_O_N) {
        o_ptr = (float*)d_out;
    } else if ((long long)out_size == OUT_S_N) {
        s_ptr = (float*)d_out;
    } else {
        o_ptr = (float*)d_out;   // fallback: at least produce the primary output
    }

    const int smem_bytes = SMEM_FLOATS * (int)sizeof(float);  // 66,560 B
    cudaFuncSetAttribute(attn_fused_kernel,
                         cudaFuncAttributeMaxDynamicSharedMemorySize, smem_bytes);

    dim3 grid(SS / BM, HH, BB);   // (32, 16, 4) = 2048 CTAs
    dim3 block(128);
    attn_fused_kernel<<<grid, block, smem_bytes>>>(q, k, v, mask, o_ptr, s_ptr);
}

// round 5
// speedup vs baseline: 1.0207x; 1.0207x over previous
#include <cuda_runtime.h>
#include <math_constants.h>

// Problem shape (fixed by the dataset)
#define BB 4
#define HH 16
#define SS 2048
#define DD 64

#define BM 128   // query rows per CTA
#define BN 64    // key/value columns per tile
#define PSS 68   // padded ps row stride (floats): kills stride-64 bank conflicts

// Dynamic smem layout (floats):
//   qst [DD][BM]   Q tile transposed: qst[d][r]        8192 f
//   ks  [DD][BN]   K tile: ks[d][c]                    4096 f
//   vs  [BN][DD]   V tile: vs[c][d]                    4096 f
//   ps  [BM][PSS]  P tile (padded)                     8704 f
#define SMEM_FLOATS (DD*BM + DD*BN + BN*DD + BM*PSS)   // 25088 f = 100,352 B

typedef unsigned long long ull;

// sm_103a packed f32x2 math: 2 FMA per issue slot, bit-exact vs scalar fma.rn
__device__ __forceinline__ void fma2(ull &d, ull a, ull b) {
    asm("fma.rn.f32x2 %0, %1, %2, %0;" : "+l"(d) : "l"(a), "l"(b));
}
__device__ __forceinline__ ull pk2(float x) {
    ull r; asm("mov.b64 %0, {%1, %1};" : "=l"(r) : "f"(x)); return r;
}
__device__ __forceinline__ void mul2(ull &d, ull a) {
    asm("mul.rn.f32x2 %0, %0, %1;" : "+l"(d) : "l"(a));
}
__device__ __forceinline__ float2 upk2(ull v) {
    float2 r; asm("mov.b64 {%0, %1}, %2;" : "=f"(r.x), "=f"(r.y) : "l"(v)); return r;
}

__global__ __launch_bounds__(256, 2)
void attn_fused_kernel(const float* __restrict__ q,
                       const float* __restrict__ k,
                       const float* __restrict__ v,
                       const int*   __restrict__ mask,
                       float* __restrict__ out_o,   // may be null
                       float* __restrict__ out_s)   // may be null
{
    extern __shared__ float sm[];
    float* qst = sm;                       // [DD][BM]
    float* ks  = qst + DD*BM;              // [DD][BN]
    float* vs  = ks  + DD*BN;              // [BN][DD]
    float* ps  = vs  + BN*DD;              // [BM][PSS]

    const int tid = threadIdx.x;
    const int tx = tid & 7;                // 0..7  -> 8 columns each
    const int ty = tid >> 3;               // 0..31 -> 4 rows each
    const int rb = blockIdx.x;             // row block (0..15)
    const int h  = blockIdx.y;
    const int b  = blockIdx.z;

    const size_t bh = (size_t)b * HH + h;
    const float* qp = q + (bh * SS + (size_t)rb * BM) * DD;  // [BM][DD]
    const float* kp = k + bh * (size_t)DD * SS;              // [DD][SS]
    const float* vp = v + bh * (size_t)SS * DD;              // [SS][DD]
    const int*   mp = mask + ((size_t)b * SS + (size_t)rb * BM) * SS; // [BM][SS]
    float* osp = out_s ? (out_s + (bh * SS + (size_t)rb * BM) * SS) : (float*)0;

    // ---- Load Q tile (BM=128 rows x 64 d), transposed into smem ----
    #pragma unroll
    for (int it = 0; it < 8; ++it) {
        int id4 = tid + it * 256;          // 0..2047 float4s
        int r  = id4 >> 4;                 // 0..127
        int d4 = (id4 & 15) * 4;
        float4 qv = *(const float4*)(qp + (size_t)r * DD + d4);
        qst[(d4 + 0) * BM + r] = qv.x;
        qst[(d4 + 1) * BM + r] = qv.y;
        qst[(d4 + 2) * BM + r] = qv.z;
        qst[(d4 + 3) * BM + r] = qv.w;
    }

    // ---- Online-softmax state (4 rows x 8 cols per thread) ----
    float m_run[4], l_run[4];
    ull o2[4][4];
    #pragma unroll
    for (int i = 0; i < 4; ++i) {
        m_run[i] = -CUDART_INF_F;
        l_run[i] = 0.f;
        #pragma unroll
        for (int jj = 0; jj < 4; ++jj) o2[i][jj] = 0ull;
    }

    for (int jt = 0; jt < SS / BN; ++jt) {
        const int s0 = jt * BN;

        __syncthreads();   // previous iter's PV readers done before overwriting tiles
        // ---- Load K and V tiles (coalesced float4); 4 iters x 256 threads ----
        #pragma unroll
        for (int it = 0; it < 4; ++it) {
            int id4 = tid + it * 256;      // 0..1023 float4s
            int r  = id4 >> 4;             // 0..63
            int c4 = (id4 & 15) * 4;
            *(float4*)(ks + r * BN + c4) = *(const float4*)(kp + (size_t)r * SS + s0 + c4);
            *(float4*)(vs + r * DD + c4) = *(const float4*)(vp + (size_t)(s0 + r) * DD + c4);
        }
        __syncthreads();

        // ---- S tile = Q*K : 4 rows x 8 cols per thread, packed f32x2 ----
        ull s2[4][4];
        #pragma unroll
        for (int i = 0; i < 4; ++i)
            #pragma unroll
            for (int jj = 0; jj < 4; ++jj) s2[i][jj] = 0ull;

        #pragma unroll 4
        for (int d = 0; d < DD; ++d) {
            const float4 a4 = *(const float4*)(qst + d * BM + 4 * ty);
            const ulonglong2 b0 = *(const ulonglong2*)(ks + d * BN + 8 * tx);
            const ulonglong2 b1 = *(const ulonglong2*)(ks + d * BN + 8 * tx + 4);
            ull ad0 = pk2(a4.x), ad1 = pk2(a4.y), ad2 = pk2(a4.z), ad3 = pk2(a4.w);
            fma2(s2[0][0], ad0, b0.x); fma2(s2[0][1], ad0, b0.y);
            fma2(s2[0][2], ad0, b1.x); fma2(s2[0][3], ad0, b1.y);
            fma2(s2[1][0], ad1, b0.x); fma2(s2[1][1], ad1, b0.y);
            fma2(s2[1][2], ad1, b1.x); fma2(s2[1][3], ad1, b1.y);
            fma2(s2[2][0], ad2, b0.x); fma2(s2[2][1], ad2, b0.y);
            fma2(s2[2][2], ad2, b1.x); fma2(s2[2][3], ad2, b1.y);
            fma2(s2[3][0], ad3, b0.x); fma2(s2[3][1], ad3, b0.y);
            fma2(s2[3][2], ad3, b1.x); fma2(s2[3][3], ad3, b1.y);
        }

        // ---- Mask, scale, write scores, online softmax update, stage P ----
        #pragma unroll
        for (int ri = 0; ri < 4; ++ri) {
            const int rloc = 4 * ty + ri;
            float sv[8];
            {
                float2 t;
                t = upk2(s2[ri][0]); sv[0] = t.x; sv[1] = t.y;
                t = upk2(s2[ri][1]); sv[2] = t.x; sv[3] = t.y;
                t = upk2(s2[ri][2]); sv[4] = t.x; sv[5] = t.y;
                t = upk2(s2[ri][3]); sv[6] = t.x; sv[7] = t.y;
            }
            const int4 m0 = *(const int4*)(mp + (size_t)rloc * SS + s0 + 8 * tx);
            const int4 m1 = *(const int4*)(mp + (size_t)rloc * SS + s0 + 8 * tx + 4);
            sv[0] = (m0.x == 0) ? -1e10f : sv[0] * 0.125f;
            sv[1] = (m0.y == 0) ? -1e10f : sv[1] * 0.125f;
            sv[2] = (m0.z == 0) ? -1e10f : sv[2] * 0.125f;
            sv[3] = (m0.w == 0) ? -1e10f : sv[3] * 0.125f;
            sv[4] = (m1.x == 0) ? -1e10f : sv[4] * 0.125f;
            sv[5] = (m1.y == 0) ? -1e10f : sv[5] * 0.125f;
            sv[6] = (m1.z == 0) ? -1e10f : sv[6] * 0.125f;
            sv[7] = (m1.w == 0) ? -1e10f : sv[7] * 0.125f;
            if (osp) {
                *(float4*)(osp + (size_t)rloc * SS + s0 + 8 * tx) =
                    make_float4(sv[0], sv[1], sv[2], sv[3]);
                *(float4*)(osp + (size_t)rloc * SS + s0 + 8 * tx + 4) =
                    make_float4(sv[4], sv[5], sv[6], sv[7]);
            }

            // row reduce across the 8 threads of this row group (consecutive lanes)
            float tm = fmaxf(fmaxf(fmaxf(sv[0], sv[1]), fmaxf(sv[2], sv[3])),
                             fmaxf(fmaxf(sv[4], sv[5]), fmaxf(sv[6], sv[7])));
            #pragma unroll
            for (int off = 4; off >= 1; off >>= 1)
                tm = fmaxf(tm, __shfl_xor_sync(0xffffffffu, tm, off));

            float mn   = fmaxf(m_run[ri], tm);
            float corr = __expf(m_run[ri] - mn);   // exp(-inf)=0 on first tile
            m_run[ri]  = mn;

            float p[8];
            float rs = 0.f;
            #pragma unroll
            for (int jj = 0; jj < 8; ++jj) { p[jj] = __expf(sv[jj] - mn); rs += p[jj]; }
            #pragma unroll
            for (int off = 4; off >= 1; off >>= 1)
                rs += __shfl_xor_sync(0xffffffffu, rs, off);

            l_run[ri] = l_run[ri] * corr + rs;
            ull c2 = pk2(corr);
            #pragma unroll
            for (int jj = 0; jj < 4; ++jj) mul2(o2[ri][jj], c2);

            *(float4*)(ps + rloc * PSS + 8 * tx)     = make_float4(p[0], p[1], p[2], p[3]);
            *(float4*)(ps + rloc * PSS + 8 * tx + 4) = make_float4(p[4], p[5], p[6], p[7]);
        }
        __syncthreads();   // ps ready

        // ---- O += P*V : packed f32x2; P via conflict-free float4, V broadcast ----
        #pragma unroll 2
        for (int c4 = 0; c4 < BN; c4 += 4) {
            float pr[4][4];
            #pragma unroll
            for (int i = 0; i < 4; ++i)
                *(float4*)pr[i] = *(const float4*)(ps + (4 * ty + i) * PSS + c4);
            #pragma unroll
            for (int cc = 0; cc < 4; ++cc) {
                const int c = c4 + cc;
                const ulonglong2 v0 = *(const ulonglong2*)(vs + c * DD + 8 * tx);
                const ulonglong2 v1 = *(const ulonglong2*)(vs + c * DD + 8 * tx + 4);
                #pragma unroll
                for (int i = 0; i < 4; ++i) {
                    ull pd = pk2(pr[i][cc]);
                    fma2(o2[i][0], pd, v0.x); fma2(o2[i][1], pd, v0.y);
                    fma2(o2[i][2], pd, v1.x); fma2(o2[i][3], pd, v1.y);
                }
            }
        }
    }

    // ---- Normalize and write O ----
    if (out_o) {
        float* op = out_o + (bh * SS + (size_t)rb * BM) * DD;
        #pragma unroll
        for (int ri = 0; ri < 4; ++ri) {
            float inv = 1.0f / l_run[ri];
            float2 t0 = upk2(o2[ri][0]);
            float2 t1 = upk2(o2[ri][1]);
            float2 t2 = upk2(o2[ri][2]);
            float2 t3 = upk2(o2[ri][3]);
            *(float4*)(op + (size_t)(4 * ty + ri) * DD + 8 * tx) =
                make_float4(t0.x * inv, t0.y * inv, t1.x * inv, t1.y * inv);
            *(float4*)(op + (size_t)(4 * ty + ri) * DD + 8 * tx + 4) =
                make_float4(t2.x * inv, t2.y * inv, t3.x * inv, t3.y * inv);
        }
    }
}

extern "C" void kernel_launch(void* const* d_in, const int* in_sizes, int n_in,
                              void* d_out, int out_size)
{
    const float* q    = (const float*)d_in[0];
    const float* k    = (const float*)d_in[1];
    const float* v    = (const float*)d_in[2];
    const int*   mask = (const int*)  d_in[3];

    const long long OUT_O_N = (long long)BB * HH * SS * DD;   // 8388608
    const long long OUT_S_N = (long long)BB * HH * SS * SS;   // 268435456

    float* o_ptr = 0;
    float* s_ptr = 0;
    if ((long long)out_size == OUT_O_N + OUT_S_N) {
        o_ptr = (float*)d_out;
        s_ptr = (float*)d_out + OUT_O_N;
    } else if ((long long)out_size == OUT_O_N) {
        o_ptr = (float*)d_out;
    } else if ((long long)out_size == OUT_S_N) {
        s_ptr = (float*)d_out;
    } else {
        o_ptr = (float*)d_out;   // fallback: at least produce the primary output
    }

    const int smem_bytes = SMEM_FLOATS * (int)sizeof(float);  // 100,352 B
    cudaFuncSetAttribute(attn_fused_kernel,
                         cudaFuncAttributeMaxDynamicSharedMemorySize, smem_bytes);

    dim3 grid(SS / BM, HH, BB);   // (16, 16, 4) = 1024 CTAs
    dim3 block(256);
    attn_fused_kernel<<<grid, block, smem_bytes>>>(q, k, v, mask, o_ptr, s_ptr);
}

// round 6
// speedup vs baseline: 1.5885x; 1.5563x over previous
#include <cuda_runtime.h>
#include <math_constants.h>
#include <cstdint>

// Problem shape (fixed by the dataset)
#define BB 4
#define HH 16
#define SS 2048
#define DD 64

#define BM 128   // query rows per CTA (8 warps x 16 rows)
#define BN 64    // key/value columns per tile
#define SQK 72   // smem row stride (floats): 8t+g / 8g+t fragment loads conflict-free

// Dynamic smem layout (floats):
//   qs [BM][SQK]  Q tile (row r, col d)
//   ks [BN][SQK]  K tile (row d, col s)   -- K global is [D][S]
//   vs [BN][SQK]  V tile (row s, col d)
//   ps [BM][SQK]  P tile (row r, col c), warp-private rows
#define QS_OFF 0
#define KS_OFF (BM*SQK)
#define VS_OFF (KS_OFF + BN*SQK)
#define PS_OFF (VS_OFF + BN*SQK)
#define SMEM_FLOATS (PS_OFF + BM*SQK)   // 27648 floats = 110,592 B

__device__ __forceinline__ uint32_t tf32_rna(float x) {
    uint32_t u; asm("cvt.rna.tf32.f32 %0, %1;" : "=r"(u) : "f"(x)); return u;
}
__device__ __forceinline__ void mma8(float* c,
    uint32_t a0, uint32_t a1, uint32_t a2, uint32_t a3,
    uint32_t b0, uint32_t b1)
{
    asm volatile(
        "mma.sync.aligned.m16n8k8.row.col.f32.tf32.tf32.f32 "
        "{%0,%1,%2,%3},{%4,%5,%6,%7},{%8,%9},{%0,%1,%2,%3};"
        : "+f"(c[0]), "+f"(c[1]), "+f"(c[2]), "+f"(c[3])
        : "r"(a0), "r"(a1), "r"(a2), "r"(a3), "r"(b0), "r"(b1));
}

// Split one fp32 into (hi tf32, lo tf32) with x ~= hi + lo (error ~2^-24 |x|)
struct Tf32Pair { uint32_t h, l; };
__device__ __forceinline__ Tf32Pair split_tf32(float x) {
    Tf32Pair r;
    r.h = tf32_rna(x);
    float lo = x - __uint_as_float(r.h);
    r.l = tf32_rna(lo);
    return r;
}

__global__ __launch_bounds__(256, 2)
void attn_mma_kernel(const float* __restrict__ q,
                     const float* __restrict__ k,
                     const float* __restrict__ v,
                     const int*   __restrict__ mask,
                     float* __restrict__ out_o,   // may be null
                     float* __restrict__ out_s)   // may be null
{
    extern __shared__ float sm[];
    float* qs = sm + QS_OFF;
    float* ks = sm + KS_OFF;
    float* vs = sm + VS_OFF;
    float* ps = sm + PS_OFF;

    const int tid  = threadIdx.x;
    const int lane = tid & 31;
    const int w    = tid >> 5;       // warp 0..7 -> rows 16w..16w+15
    const int g    = lane >> 2;      // group 0..7
    const int t    = lane & 3;       // thread-in-group 0..3

    const int rb = blockIdx.x;
    const int h  = blockIdx.y;
    const int b  = blockIdx.z;

    const size_t bh = (size_t)b * HH + h;
    const float* qp = q + (bh * SS + (size_t)rb * BM) * DD;   // [BM][DD]
    const float* kp = k + bh * (size_t)DD * SS;               // [DD][SS]
    const float* vp = v + bh * (size_t)SS * DD;               // [SS][DD]
    const int*   mp = mask + ((size_t)b * SS + (size_t)rb * BM) * SS;  // [BM][SS]
    float* osp = out_s ? (out_s + (bh * SS + (size_t)rb * BM) * SS) : (float*)0;

    // ---- Load Q tile (128 x 64) into qs, stride SQK ----
    #pragma unroll
    for (int it = 0; it < 8; ++it) {
        int id4 = tid + it * 256;
        int r  = id4 >> 4;
        int d4 = (id4 & 15) * 4;
        *(float4*)(qs + r * SQK + d4) = *(const float4*)(qp + (size_t)r * DD + d4);
    }

    const int row_l0 = 16 * w + g;       // local rows this thread's fragments touch
    const int row_l1 = row_l0 + 8;

    float oacc[8][4];                    // 8 d-tiles x (r0c0, r0c1, r1c0, r1c1)
    float m0 = -CUDART_INF_F, m1 = -CUDART_INF_F, l0 = 0.f, l1 = 0.f;
    #pragma unroll
    for (int j = 0; j < 8; ++j)
        oacc[j][0] = oacc[j][1] = oacc[j][2] = oacc[j][3] = 0.f;

    for (int jt = 0; jt < SS / BN; ++jt) {
        const int s0 = jt * BN;

        __syncthreads();   // previous tile's consumers done before overwrite
        #pragma unroll
        for (int it = 0; it < 4; ++it) {
            int id4 = tid + it * 256;
            int r  = id4 >> 4;
            int c4 = (id4 & 15) * 4;
            *(float4*)(ks + r * SQK + c4) = *(const float4*)(kp + (size_t)r * SS + s0 + c4);
            *(float4*)(vs + r * SQK + c4) = *(const float4*)(vp + (size_t)(s0 + r) * DD + c4);
        }
        __syncthreads();

        // ---- S = Q K : 16x64 per warp, 3xTF32 ----
        float sacc[8][4];
        #pragma unroll
        for (int j = 0; j < 8; ++j)
            sacc[j][0] = sacc[j][1] = sacc[j][2] = sacc[j][3] = 0.f;

        {
            const float* q0 = qs + row_l0 * SQK;
            const float* q1 = qs + row_l1 * SQK;
            #pragma unroll 1
            for (int k0 = 0; k0 < DD; k0 += 8) {
                Tf32Pair a0 = split_tf32(q0[k0 + t]);
                Tf32Pair a1 = split_tf32(q1[k0 + t]);
                Tf32Pair a2 = split_tf32(q0[k0 + t + 4]);
                Tf32Pair a3 = split_tf32(q1[k0 + t + 4]);
                const float* kb  = ks + (k0 + t) * SQK + g;
                const float* kb4 = ks + (k0 + t + 4) * SQK + g;
                #pragma unroll
                for (int j = 0; j < 8; ++j) {
                    Tf32Pair b0 = split_tf32(kb[8 * j]);
                    Tf32Pair b1 = split_tf32(kb4[8 * j]);
                    mma8(sacc[j], a0.h, a1.h, a2.h, a3.h, b0.h, b1.h);
                    mma8(sacc[j], a0.h, a1.h, a2.h, a3.h, b0.l, b1.l);
                    mma8(sacc[j], a0.l, a1.l, a2.l, a3.l, b0.h, b1.h);
                }
            }
        }

        // ---- Mask, scale, store scores, intra-warp online softmax ----
        float rmax0 = -CUDART_INF_F, rmax1 = -CUDART_INF_F;
        const int coff0 = s0 + 2 * t;
        #pragma unroll
        for (int j = 0; j < 8; ++j) {
            const int coff = coff0 + 8 * j;
            int2 mr0 = *(const int2*)(mp + (size_t)row_l0 * SS + coff);
            int2 mr1 = *(const int2*)(mp + (size_t)row_l1 * SS + coff);
            float s00 = (mr0.x == 0) ? -1e10f : sacc[j][0] * 0.125f;
            float s01 = (mr0.y == 0) ? -1e10f : sacc[j][1] * 0.125f;
            float s10 = (mr1.x == 0) ? -1e10f : sacc[j][2] * 0.125f;
            float s11 = (mr1.y == 0) ? -1e10f : sacc[j][3] * 0.125f;
            if (osp) {
                *(float2*)(osp + (size_t)row_l0 * SS + coff) = make_float2(s00, s01);
                *(float2*)(osp + (size_t)row_l1 * SS + coff) = make_float2(s10, s11);
            }
            sacc[j][0] = s00; sacc[j][1] = s01; sacc[j][2] = s10; sacc[j][3] = s11;
            rmax0 = fmaxf(rmax0, fmaxf(s00, s01));
            rmax1 = fmaxf(rmax1, fmaxf(s10, s11));
        }
        rmax0 = fmaxf(rmax0, __shfl_xor_sync(0xffffffffu, rmax0, 1));
        rmax0 = fmaxf(rmax0, __shfl_xor_sync(0xffffffffu, rmax0, 2));
        rmax1 = fmaxf(rmax1, __shfl_xor_sync(0xffffffffu, rmax1, 1));
        rmax1 = fmaxf(rmax1, __shfl_xor_sync(0xffffffffu, rmax1, 2));

        float mn0 = fmaxf(m0, rmax0), mn1 = fmaxf(m1, rmax1);
        float corr0 = __expf(m0 - mn0), corr1 = __expf(m1 - mn1);
        m0 = mn0; m1 = mn1;

        float rs0 = 0.f, rs1 = 0.f;
        float* p0 = ps + row_l0 * SQK + 2 * t;
        float* p1 = ps + row_l1 * SQK + 2 * t;
        #pragma unroll
        for (int j = 0; j < 8; ++j) {
            float p00 = __expf(sacc[j][0] - mn0);
            float p01 = __expf(sacc[j][1] - mn0);
            float p10 = __expf(sacc[j][2] - mn1);
            float p11 = __expf(sacc[j][3] - mn1);
            rs0 += p00 + p01; rs1 += p10 + p11;
            *(float2*)(p0 + 8 * j) = make_float2(p00, p01);
            *(float2*)(p1 + 8 * j) = make_float2(p10, p11);
        }
        rs0 += __shfl_xor_sync(0xffffffffu, rs0, 1);
        rs0 += __shfl_xor_sync(0xffffffffu, rs0, 2);
        rs1 += __shfl_xor_sync(0xffffffffu, rs1, 1);
        rs1 += __shfl_xor_sync(0xffffffffu, rs1, 2);
        l0 = l0 * corr0 + rs0;
        l1 = l1 * corr1 + rs1;
        #pragma unroll
        for (int j = 0; j < 8; ++j) {
            oacc[j][0] *= corr0; oacc[j][1] *= corr0;
            oacc[j][2] *= corr1; oacc[j][3] *= corr1;
        }
        __syncwarp();   // ps rows are warp-private; order STS -> LDS within warp

        // ---- O += P V : 16x64 per warp, 3xTF32, contraction over c ----
        {
            const float* pr0 = ps + row_l0 * SQK;
            const float* pr1 = ps + row_l1 * SQK;
            #pragma unroll 1
            for (int k0 = 0; k0 < BN; k0 += 8) {
                Tf32Pair a0 = split_tf32(pr0[k0 + t]);
                Tf32Pair a1 = split_tf32(pr1[k0 + t]);
                Tf32Pair a2 = split_tf32(pr0[k0 + t + 4]);
                Tf32Pair a3 = split_tf32(pr1[k0 + t + 4]);
                const float* vb  = vs + (k0 + t) * SQK + g;
                const float* vb4 = vs + (k0 + t + 4) * SQK + g;
                #pragma unroll
                for (int j = 0; j < 8; ++j) {
                    Tf32Pair b0 = split_tf32(vb[8 * j]);
                    Tf32Pair b1 = split_tf32(vb4[8 * j]);
                    mma8(oacc[j], a0.h, a1.h, a2.h, a3.h, b0.h, b1.h);
                    mma8(oacc[j], a0.h, a1.h, a2.h, a3.h, b0.l, b1.l);
                    mma8(oacc[j], a0.l, a1.l, a2.l, a3.l, b0.h, b1.h);
                }
            }
        }
    }

    // ---- Normalize and write O ----
    if (out_o) {
        float inv0 = 1.0f / l0, inv1 = 1.0f / l1;
        float* op = out_o + (bh * SS + (size_t)rb * BM) * DD;
        #pragma unroll
        for (int j = 0; j < 8; ++j) {
            int dc = 8 * j + 2 * t;
            *(float2*)(op + (size_t)row_l0 * DD + dc) =
                make_float2(oacc[j][0] * inv0, oacc[j][1] * inv0);
            *(float2*)(op + (size_t)row_l1 * DD + dc) =
                make_float2(oacc[j][2] * inv1, oacc[j][3] * inv1);
        }
    }
}

extern "C" void kernel_launch(void* const* d_in, const int* in_sizes, int n_in,
                              void* d_out, int out_size)
{
    const float* q    = (const float*)d_in[0];
    const float* k    = (const float*)d_in[1];
    const float* v    = (const float*)d_in[2];
    const int*   mask = (const int*)  d_in[3];

    const long long OUT_O_N = (long long)BB * HH * SS * DD;   // 8388608
    const long long OUT_S_N = (long long)BB * HH * SS * SS;   // 268435456

    float* o_ptr = 0;
    float* s_ptr = 0;
    if ((long long)out_size == OUT_O_N + OUT_S_N) {
        o_ptr = (float*)d_out;
        s_ptr = (float*)d_out + OUT_O_N;
    } else if ((long long)out_size == OUT_O_N) {
        o_ptr = (float*)d_out;
    } else if ((long long)out_size == OUT_S_N) {
        s_ptr = (float*)d_out;
    } else {
        o_ptr = (float*)d_out;   // fallback: at least produce the primary output
    }

    const int smem_bytes = SMEM_FLOATS * (int)sizeof(float);  // 110,592 B
    cudaFuncSetAttribute(attn_mma_kernel,
                         cudaFuncAttributeMaxDynamicSharedMemorySize, smem_bytes);

    dim3 grid(SS / BM, HH, BB);   // (16, 16, 4) = 1024 CTAs
    dim3 block(256);
    attn_mma_kernel<<<grid, block, smem_bytes>>>(q, k, v, mask, o_ptr, s_ptr);
}